// round 1
// baseline (speedup 1.0000x reference)
#include <cuda_runtime.h>
#include <math.h>

// Problem constants
#define BB   2
#define SS   2048
#define DD   768
#define HH   12
#define HDIM 64
#define QKVD 2304           // 3*D per token
#define NTOK (BB*SS)        // 4096

// Scratch (allocation-free rule: __device__ globals)
__device__ float g_qkv[(size_t)NTOK * QKVD];   // [4096, 2304]
__device__ float g_attn[(size_t)NTOK * DD];    // [4096, 768]

// ---------------------------------------------------------------------------
// SGEMM NT:  C[M,N] = A[M,K] * B[N,K]^T   (all row-major, M%128==0, N%128==0, K%16==0)
// 128x128x16 tiles, 256 threads, 8x8 per thread as 2x2 strips of 4x4.
// ---------------------------------------------------------------------------
__global__ __launch_bounds__(256) void sgemm_nt(const float* __restrict__ A,
                                                const float* __restrict__ B,
                                                float* __restrict__ C,
                                                int M, int N, int K)
{
    __shared__ float As[16][128];
    __shared__ float Bs[16][128];

    const int tid = threadIdx.x;
    const int tx  = tid & 15;        // 0..15 -> N strips
    const int ty  = tid >> 4;        // 0..15 -> M strips
    const int bm  = blockIdx.y * 128;
    const int bn  = blockIdx.x * 128;

    float acc[8][8];
#pragma unroll
    for (int i = 0; i < 8; i++)
#pragma unroll
        for (int j = 0; j < 8; j++) acc[i][j] = 0.f;

    const int lr  = tid >> 1;          // row within tile 0..127
    const int lk4 = (tid & 1) * 2;     // first float4 index within the 16-wide k tile

    const float4* A4 = (const float4*)(A + (size_t)(bm + lr) * K);
    const float4* B4 = (const float4*)(B + (size_t)(bn + lr) * K);

    for (int kt = 0; kt < K; kt += 16) {
        const int k4base = (kt >> 2) + lk4;
#pragma unroll
        for (int i = 0; i < 2; i++) {
            float4 a = A4[k4base + i];
            float4 b = B4[k4base + i];
            int kk = (lk4 + i) * 4;
            As[kk + 0][lr] = a.x; As[kk + 1][lr] = a.y;
            As[kk + 2][lr] = a.z; As[kk + 3][lr] = a.w;
            Bs[kk + 0][lr] = b.x; Bs[kk + 1][lr] = b.y;
            Bs[kk + 2][lr] = b.z; Bs[kk + 3][lr] = b.w;
        }
        __syncthreads();

#pragma unroll
        for (int k = 0; k < 16; k++) {
            float ar[8], br[8];
            float4 a0 = *(const float4*)&As[k][ty * 4];
            float4 a1 = *(const float4*)&As[k][64 + ty * 4];
            float4 b0 = *(const float4*)&Bs[k][tx * 4];
            float4 b1 = *(const float4*)&Bs[k][64 + tx * 4];
            ar[0]=a0.x; ar[1]=a0.y; ar[2]=a0.z; ar[3]=a0.w;
            ar[4]=a1.x; ar[5]=a1.y; ar[6]=a1.z; ar[7]=a1.w;
            br[0]=b0.x; br[1]=b0.y; br[2]=b0.z; br[3]=b0.w;
            br[4]=b1.x; br[5]=b1.y; br[6]=b1.z; br[7]=b1.w;
#pragma unroll
            for (int i = 0; i < 8; i++)
#pragma unroll
                for (int j = 0; j < 8; j++)
                    acc[i][j] += ar[i] * br[j];
        }
        __syncthreads();
    }

#pragma unroll
    for (int i = 0; i < 8; i++) {
        int rr = (i < 4) ? (ty * 4 + i) : (64 + ty * 4 + (i - 4));
        float* Cr = C + (size_t)(bm + rr) * N + bn;
        float4 v0 = make_float4(acc[i][0], acc[i][1], acc[i][2], acc[i][3]);
        float4 v1 = make_float4(acc[i][4], acc[i][5], acc[i][6], acc[i][7]);
        ((float4*)Cr)[tx]        = v0;
        ((float4*)(Cr + 64))[tx] = v1;
    }
}

// ---------------------------------------------------------------------------
// Fused RoPE + sliding-window attention.
// grid: (S/128, B*H). block: 256 threads. 2 threads per query (key-split).
// smem: K[256][68] and V[256][68] fp32 (pitch 68 -> LDS.128 conflict-free).
// ---------------------------------------------------------------------------
#define KSPAN  256
#define KPITCH 68
#define ATTN_SMEM (2 * KSPAN * KPITCH * 4)

__device__ __forceinline__ void rope4(int i, float pos, float4 x, float4 y,
                                      float4& lo, float4& hi)
{
    const float FCOEF = -0.41524101186091903f;  // -log2(10000)/32
    float f, sn, cs;
    f = pos * exp2f((float)(4 * i + 0) * FCOEF); sincosf(f, &sn, &cs);
    lo.x = x.x * cs - y.x * sn;  hi.x = y.x * cs + x.x * sn;
    f = pos * exp2f((float)(4 * i + 1) * FCOEF); sincosf(f, &sn, &cs);
    lo.y = x.y * cs - y.y * sn;  hi.y = y.y * cs + x.y * sn;
    f = pos * exp2f((float)(4 * i + 2) * FCOEF); sincosf(f, &sn, &cs);
    lo.z = x.z * cs - y.z * sn;  hi.z = y.z * cs + x.z * sn;
    f = pos * exp2f((float)(4 * i + 3) * FCOEF); sincosf(f, &sn, &cs);
    lo.w = x.w * cs - y.w * sn;  hi.w = y.w * cs + x.w * sn;
}

__global__ __launch_bounds__(256) void attn_kernel(const int* __restrict__ pos_ids,
                                                   float* __restrict__ out_g)
{
    extern __shared__ float sm[];
    float* Ks = sm;
    float* Vs = sm + KSPAN * KPITCH;

    const int tid = threadIdx.x;
    const int qb  = blockIdx.x;          // query tile (0..15)
    const int bh  = blockIdx.y;          // 0..23
    const int b   = bh / HH;
    const int h   = bh % HH;
    const int kstart = qb * 128 - 64;
    const float L2E = 1.4426950408889634f;

    // ---- load + RoPE K rows, copy V rows into smem ----
    for (int r = tid; r < KSPAN; r += 256) {
        int kg = kstart + r;
        if (kg >= 0 && kg < SS) {
            const float* kp = g_qkv + ((size_t)(b * SS + kg)) * QKVD + DD + h * HDIM;
            const float* vp = kp + DD;
            float pos = (float)pos_ids[b * SS + kg];
            float* kd = Ks + r * KPITCH;
            float* vd = Vs + r * KPITCH;
#pragma unroll
            for (int i = 0; i < 8; i++) {
                float4 x = ((const float4*)kp)[i];
                float4 y = ((const float4*)kp)[i + 8];
                float4 lo, hi;
                rope4(i, pos, x, y, lo, hi);
                ((float4*)kd)[i]     = lo;
                ((float4*)kd)[i + 8] = hi;
            }
#pragma unroll
            for (int i = 0; i < 16; i++)
                ((float4*)vd)[i] = ((const float4*)vp)[i];
        }
    }

    // ---- load + RoPE Q row into registers (2 threads share a query) ----
    const int qi    = tid & 127;
    const int half  = tid >> 7;
    const int qglob = qb * 128 + qi;
    float q[64];
    {
        const float* qp = g_qkv + ((size_t)(b * SS + qglob)) * QKVD + h * HDIM;
        float pos = (float)pos_ids[b * SS + qglob];
#pragma unroll
        for (int i = 0; i < 8; i++) {
            float4 x = ((const float4*)qp)[i];
            float4 y = ((const float4*)qp)[i + 8];
            float4 lo, hi;
            rope4(i, pos, x, y, lo, hi);
            q[i*4+0]=lo.x; q[i*4+1]=lo.y; q[i*4+2]=lo.z; q[i*4+3]=lo.w;
            q[32+i*4+0]=hi.x; q[32+i*4+1]=hi.y; q[32+i*4+2]=hi.z; q[32+i*4+3]=hi.w;
        }
    }
    __syncthreads();

    // exact per-thread key window, split between the two halves
    const int lo_j = max(0, qglob - 64) - kstart;
    const int hi_j = min(SS - 1, qglob + 64) - kstart;
    int jbeg, jend;
    if (half == 0) { jbeg = lo_j;      jend = min(hi_j, lo_j + 64); }
    else           { jbeg = lo_j + 65; jend = hi_j; }

    float m = -INFINITY, l = 0.f;
    float o[64];
#pragma unroll
    for (int d = 0; d < 64; d++) o[d] = 0.f;

    for (int j = jbeg; j <= jend; j++) {
        const float4* kr = (const float4*)(Ks + j * KPITCH);
        float s0 = 0.f, s1 = 0.f, s2 = 0.f, s3 = 0.f;
#pragma unroll
        for (int d4 = 0; d4 < 16; d4++) {
            float4 kv = kr[d4];
            s0 += q[d4*4+0] * kv.x;
            s1 += q[d4*4+1] * kv.y;
            s2 += q[d4*4+2] * kv.z;
            s3 += q[d4*4+3] * kv.w;
        }
        float s = ((s0 + s1) + (s2 + s3)) * 0.125f;   // HD^-0.5

        if (s > m) {
            float alpha = exp2f((m - s) * L2E);
            l *= alpha;
#pragma unroll
            for (int d = 0; d < 64; d++) o[d] *= alpha;
            m = s;
        }
        float p = exp2f((s - m) * L2E);
        l += p;

        const float4* vr = (const float4*)(Vs + j * KPITCH);
#pragma unroll
        for (int d4 = 0; d4 < 16; d4++) {
            float4 vv = vr[d4];
            o[d4*4+0] += p * vv.x;
            o[d4*4+1] += p * vv.y;
            o[d4*4+2] += p * vv.z;
            o[d4*4+3] += p * vv.w;
        }
    }

    // ---- merge the two halves via smem (reuse Ks region) ----
    __syncthreads();
    float* red = sm;   // 128 rows of 66 floats: m, l, o[64]
    if (half == 1) {
        float* rr = red + qi * 66;
        rr[0] = m; rr[1] = l;
#pragma unroll
        for (int d = 0; d < 64; d++) rr[2 + d] = o[d];
    }
    __syncthreads();
    if (half == 0) {
        const float* rr = red + qi * 66;
        float m1 = rr[0], l1 = rr[1];
        float M  = fmaxf(m, m1);
        float a0 = exp2f((m  - M) * L2E);
        float a1 = exp2f((m1 - M) * L2E);
        float inv = 1.f / (l * a0 + l1 * a1);
        float* og = g_attn + ((size_t)(b * SS + qglob)) * DD + h * HDIM;
#pragma unroll
        for (int d4 = 0; d4 < 16; d4++) {
            float4 v;
            v.x = (o[d4*4+0] * a0 + rr[2 + d4*4+0] * a1) * inv;
            v.y = (o[d4*4+1] * a0 + rr[2 + d4*4+1] * a1) * inv;
            v.z = (o[d4*4+2] * a0 + rr[2 + d4*4+2] * a1) * inv;
            v.w = (o[d4*4+3] * a0 + rr[2 + d4*4+3] * a1) * inv;
            ((float4*)og)[d4] = v;
        }
    }
    (void)out_g;
}

// ---------------------------------------------------------------------------
extern "C" void kernel_launch(void* const* d_in, const int* in_sizes, int n_in,
                              void* d_out, int out_size)
{
    const float* hidden = (const float*)d_in[0];
    const float* wqkv   = (const float*)d_in[1];
    const float* wo     = (const float*)d_in[2];
    const int*   pos    = (const int*)d_in[4];
    float*       out    = (float*)d_out;

    float *qkv_ptr, *attn_ptr;
    cudaGetSymbolAddress((void**)&qkv_ptr,  g_qkv);
    cudaGetSymbolAddress((void**)&attn_ptr, g_attn);

    cudaFuncSetAttribute(attn_kernel, cudaFuncAttributeMaxDynamicSharedMemorySize,
                         ATTN_SMEM);

    // 1) QKV = hidden @ Wqkv^T    [4096,2304]
    sgemm_nt<<<dim3(QKVD / 128, NTOK / 128), 256>>>(hidden, wqkv, qkv_ptr,
                                                    NTOK, QKVD, DD);
    // 2) fused RoPE + sliding-window attention -> g_attn [4096,768]
    attn_kernel<<<dim3(SS / 128, BB * HH), 256, ATTN_SMEM>>>(pos, attn_ptr);
    // 3) out = g_attn @ Wo^T      [4096,768]
    sgemm_nt<<<dim3(DD / 128, NTOK / 128), 256>>>(attn_ptr, wo, out,
                                                  NTOK, DD, DD);
}

// round 3
// speedup vs baseline: 2.0445x; 2.0445x over previous
#include <cuda_runtime.h>
#include <math.h>
#include <stdint.h>

// Problem constants
#define BB   2
#define SS   2048
#define DD   768
#define HH   12
#define HDIM 64
#define QKVD 2304           // 3*D per token
#define NTOK (BB*SS)        // 4096

// Scratch (allocation-free rule: __device__ globals)
__device__ float g_qkv[(size_t)NTOK * QKVD];   // [4096, 2304]
__device__ float g_attn[(size_t)NTOK * DD];    // [4096, 768]

__device__ __forceinline__ float to_tf32(float x) {
    uint32_t u;
    asm("cvt.rna.tf32.f32 %0, %1;" : "=r"(u) : "f"(x));
    return __uint_as_float(u);
}

__device__ __forceinline__ void mma_tf32(float c[4], const uint32_t a[4], const uint32_t b[2]) {
    asm volatile(
        "mma.sync.aligned.m16n8k8.row.col.f32.tf32.tf32.f32 "
        "{%0,%1,%2,%3}, {%4,%5,%6,%7}, {%8,%9}, {%0,%1,%2,%3};"
        : "+f"(c[0]), "+f"(c[1]), "+f"(c[2]), "+f"(c[3])
        : "r"(a[0]), "r"(a[1]), "r"(a[2]), "r"(a[3]), "r"(b[0]), "r"(b[1]));
}

// ---------------------------------------------------------------------------
// tf32 mma.sync GEMM NT: C[M,N] = A[M,K] * B[N,K]^T  (row-major, M,N %128, K %32)
// CTA 128x128x32, 8 warps (2Mx4N), warp tile 64x32. Fragment-ordered smem.
// ---------------------------------------------------------------------------
#define ASUB 132                 // padded A subtile stride (floats); data = 128
#define BSUB 68                  // padded B subtile stride (floats); data = 64
#define AOFF 0
#define BOFF (32 * ASUB)         // 4224 floats
#define BUFF (32 * ASUB + 64 * BSUB)   // 8576 floats per buffer
#define GEMM_SMEM (2 * BUFF * 4)       // 68608 bytes

__global__ __launch_bounds__(256, 1) void gemm_mma_tf32(const float* __restrict__ A,
                                                        const float* __restrict__ B,
                                                        float* __restrict__ C,
                                                        int M, int N, int K)
{
    extern __shared__ float smf[];
    const int tid    = threadIdx.x;
    const int wid    = tid >> 5;
    const int lane   = tid & 31;
    const int bm     = blockIdx.y * 128;
    const int bn     = blockIdx.x * 128;
    const int warp_m = wid >> 2;   // 0..1
    const int warp_n = wid & 3;    // 0..3

    float acc[4][4][4];
#pragma unroll
    for (int a = 0; a < 4; a++)
#pragma unroll
        for (int b = 0; b < 4; b++)
#pragma unroll
            for (int r = 0; r < 4; r++) acc[a][b][r] = 0.f;

    // ---- global-load / smem-store geometry (per thread) ----
    const int r0 = tid >> 3;          // base row 0..31 (+32*i)
    const int c4 = tid & 7;           // float4 index along 32-wide k-chunk
    const int ki_st = c4 >> 1;        // k-subtile this thread's float4 lands in
    const int qpar  = c4 & 1;         // which half (cc>=4) of the subtile

    // smem base offsets for e=0 of each of the 4 rows handled (i=0..3)
    int stA[4], stB[4];
    const float* gA[4];
    const float* gB[4];
#pragma unroll
    for (int i = 0; i < 4; i++) {
        const int r  = r0 + 32 * i;        // 0..127
        const int mi = r >> 4, rr = r & 15;
        const int ni = r >> 3, nn = r & 7;
        stA[i] = AOFF + (mi * 4 + ki_st) * ASUB + (rr & 7) * 16 + (rr >> 3) + 2 * qpar;
        stB[i] = BOFF + (ni * 4 + ki_st) * BSUB + nn * 8 + qpar;
        gA[i]  = A + (size_t)(bm + r) * K + c4 * 4;
        gB[i]  = B + (size_t)(bn + r) * K + c4 * 4;
    }

    // compute-side fragment base offsets
    int afb[4], bfb[4];
#pragma unroll
    for (int a = 0; a < 4; a++)
        afb[a] = AOFF + (warp_m * 4 + a) * 4 * ASUB + lane * 4;
#pragma unroll
    for (int b = 0; b < 4; b++)
        bfb[b] = BOFF + (warp_n * 4 + b) * 4 * BSUB + lane * 2;

    const int nchunks = K >> 5;
    float4 la[4], lb[4];

    // prologue: load + store chunk 0
#pragma unroll
    for (int i = 0; i < 4; i++) {
        la[i] = *(const float4*)gA[i];
        lb[i] = *(const float4*)gB[i];
    }
    {
        float* s = smf;   // buffer 0
#pragma unroll
        for (int i = 0; i < 4; i++) {
            s[stA[i] + 0]  = to_tf32(la[i].x);
            s[stA[i] + 4]  = to_tf32(la[i].y);
            s[stA[i] + 8]  = to_tf32(la[i].z);
            s[stA[i] + 12] = to_tf32(la[i].w);
            s[stB[i] + 0]  = to_tf32(lb[i].x);
            s[stB[i] + 2]  = to_tf32(lb[i].y);
            s[stB[i] + 4]  = to_tf32(lb[i].z);
            s[stB[i] + 6]  = to_tf32(lb[i].w);
        }
    }
    __syncthreads();

    for (int c = 0; c < nchunks; c++) {
        if (c + 1 < nchunks) {
            const int off = (c + 1) * 32;
#pragma unroll
            for (int i = 0; i < 4; i++) {
                la[i] = *(const float4*)(gA[i] + off);
                lb[i] = *(const float4*)(gB[i] + off);
            }
        }

        const float* s = smf + (c & 1) * BUFF;
#pragma unroll
        for (int ki = 0; ki < 4; ki++) {
            uint32_t af[4][4], bf[4][2];
#pragma unroll
            for (int a = 0; a < 4; a++) {
                float4 v = *(const float4*)(s + afb[a] + ki * ASUB);
                af[a][0] = __float_as_uint(v.x);
                af[a][1] = __float_as_uint(v.y);
                af[a][2] = __float_as_uint(v.z);
                af[a][3] = __float_as_uint(v.w);
            }
#pragma unroll
            for (int b = 0; b < 4; b++) {
                float2 v = *(const float2*)(s + bfb[b] + ki * BSUB);
                bf[b][0] = __float_as_uint(v.x);
                bf[b][1] = __float_as_uint(v.y);
            }
#pragma unroll
            for (int a = 0; a < 4; a++)
#pragma unroll
                for (int b = 0; b < 4; b++)
                    mma_tf32(acc[a][b], af[a], bf[b]);
        }

        if (c + 1 < nchunks) {
            float* d = smf + ((c + 1) & 1) * BUFF;
#pragma unroll
            for (int i = 0; i < 4; i++) {
                d[stA[i] + 0]  = to_tf32(la[i].x);
                d[stA[i] + 4]  = to_tf32(la[i].y);
                d[stA[i] + 8]  = to_tf32(la[i].z);
                d[stA[i] + 12] = to_tf32(la[i].w);
                d[stB[i] + 0]  = to_tf32(lb[i].x);
                d[stB[i] + 2]  = to_tf32(lb[i].y);
                d[stB[i] + 4]  = to_tf32(lb[i].z);
                d[stB[i] + 6]  = to_tf32(lb[i].w);
            }
            __syncthreads();
        }
    }

    // epilogue: direct float2 stores
    const int g = lane >> 2, t = lane & 3;
#pragma unroll
    for (int a = 0; a < 4; a++) {
        const int row = bm + warp_m * 64 + a * 16 + g;
#pragma unroll
        for (int b = 0; b < 4; b++) {
            const int col = bn + warp_n * 32 + b * 8 + 2 * t;
            *(float2*)(C + (size_t)row * N + col)       = make_float2(acc[a][b][0], acc[a][b][1]);
            *(float2*)(C + (size_t)(row + 8) * N + col) = make_float2(acc[a][b][2], acc[a][b][3]);
        }
    }
}

// ---------------------------------------------------------------------------
// Fused RoPE + sliding-window attention (unchanged).
// ---------------------------------------------------------------------------
#define KSPAN  256
#define KPITCH 68
#define ATTN_SMEM (2 * KSPAN * KPITCH * 4)

__device__ __forceinline__ void rope4(int i, float pos, float4 x, float4 y,
                                      float4& lo, float4& hi)
{
    const float FCOEF = -0.41524101186091903f;  // -log2(10000)/32
    float f, sn, cs;
    f = pos * exp2f((float)(4 * i + 0) * FCOEF); sincosf(f, &sn, &cs);
    lo.x = x.x * cs - y.x * sn;  hi.x = y.x * cs + x.x * sn;
    f = pos * exp2f((float)(4 * i + 1) * FCOEF); sincosf(f, &sn, &cs);
    lo.y = x.y * cs - y.y * sn;  hi.y = y.y * cs + x.y * sn;
    f = pos * exp2f((float)(4 * i + 2) * FCOEF); sincosf(f, &sn, &cs);
    lo.z = x.z * cs - y.z * sn;  hi.z = y.z * cs + x.z * sn;
    f = pos * exp2f((float)(4 * i + 3) * FCOEF); sincosf(f, &sn, &cs);
    lo.w = x.w * cs - y.w * sn;  hi.w = y.w * cs + x.w * sn;
}

__global__ __launch_bounds__(256) void attn_kernel(const int* __restrict__ pos_ids,
                                                   float* __restrict__ out_g)
{
    extern __shared__ float sm[];
    float* Ks = sm;
    float* Vs = sm + KSPAN * KPITCH;

    const int tid = threadIdx.x;
    const int qb  = blockIdx.x;
    const int bh  = blockIdx.y;
    const int b   = bh / HH;
    const int h   = bh % HH;
    const int kstart = qb * 128 - 64;
    const float L2E = 1.4426950408889634f;

    for (int r = tid; r < KSPAN; r += 256) {
        int kg = kstart + r;
        if (kg >= 0 && kg < SS) {
            const float* kp = g_qkv + ((size_t)(b * SS + kg)) * QKVD + DD + h * HDIM;
            const float* vp = kp + DD;
            float pos = (float)pos_ids[b * SS + kg];
            float* kd = Ks + r * KPITCH;
            float* vd = Vs + r * KPITCH;
#pragma unroll
            for (int i = 0; i < 8; i++) {
                float4 x = ((const float4*)kp)[i];
                float4 y = ((const float4*)kp)[i + 8];
                float4 lo, hi;
                rope4(i, pos, x, y, lo, hi);
                ((float4*)kd)[i]     = lo;
                ((float4*)kd)[i + 8] = hi;
            }
#pragma unroll
            for (int i = 0; i < 16; i++)
                ((float4*)vd)[i] = ((const float4*)vp)[i];
        }
    }

    const int qi    = tid & 127;
    const int half  = tid >> 7;
    const int qglob = qb * 128 + qi;
    float q[64];
    {
        const float* qp = g_qkv + ((size_t)(b * SS + qglob)) * QKVD + h * HDIM;
        float pos = (float)pos_ids[b * SS + qglob];
#pragma unroll
        for (int i = 0; i < 8; i++) {
            float4 x = ((const float4*)qp)[i];
            float4 y = ((const float4*)qp)[i + 8];
            float4 lo, hi;
            rope4(i, pos, x, y, lo, hi);
            q[i*4+0]=lo.x; q[i*4+1]=lo.y; q[i*4+2]=lo.z; q[i*4+3]=lo.w;
            q[32+i*4+0]=hi.x; q[32+i*4+1]=hi.y; q[32+i*4+2]=hi.z; q[32+i*4+3]=hi.w;
        }
    }
    __syncthreads();

    const int lo_j = max(0, qglob - 64) - kstart;
    const int hi_j = min(SS - 1, qglob + 64) - kstart;
    int jbeg, jend;
    if (half == 0) { jbeg = lo_j;      jend = min(hi_j, lo_j + 64); }
    else           { jbeg = lo_j + 65; jend = hi_j; }

    float m = -INFINITY, l = 0.f;
    float o[64];
#pragma unroll
    for (int d = 0; d < 64; d++) o[d] = 0.f;

    for (int j = jbeg; j <= jend; j++) {
        const float4* kr = (const float4*)(Ks + j * KPITCH);
        float s0 = 0.f, s1 = 0.f, s2 = 0.f, s3 = 0.f;
#pragma unroll
        for (int d4 = 0; d4 < 16; d4++) {
            float4 kv = kr[d4];
            s0 += q[d4*4+0] * kv.x;
            s1 += q[d4*4+1] * kv.y;
            s2 += q[d4*4+2] * kv.z;
            s3 += q[d4*4+3] * kv.w;
        }
        float s = ((s0 + s1) + (s2 + s3)) * 0.125f;

        if (s > m) {
            float alpha = exp2f((m - s) * L2E);
            l *= alpha;
#pragma unroll
            for (int d = 0; d < 64; d++) o[d] *= alpha;
            m = s;
        }
        float p = exp2f((s - m) * L2E);
        l += p;

        const float4* vr = (const float4*)(Vs + j * KPITCH);
#pragma unroll
        for (int d4 = 0; d4 < 16; d4++) {
            float4 vv = vr[d4];
            o[d4*4+0] += p * vv.x;
            o[d4*4+1] += p * vv.y;
            o[d4*4+2] += p * vv.z;
            o[d4*4+3] += p * vv.w;
        }
    }

    __syncthreads();
    float* red = sm;
    if (half == 1) {
        float* rr = red + qi * 66;
        rr[0] = m; rr[1] = l;
#pragma unroll
        for (int d = 0; d < 64; d++) rr[2 + d] = o[d];
    }
    __syncthreads();
    if (half == 0) {
        const float* rr = red + qi * 66;
        float m1 = rr[0], l1 = rr[1];
        float M  = fmaxf(m, m1);
        float a0 = exp2f((m  - M) * L2E);
        float a1 = exp2f((m1 - M) * L2E);
        float inv = 1.f / (l * a0 + l1 * a1);
        float* og = g_attn + ((size_t)(b * SS + qglob)) * DD + h * HDIM;
#pragma unroll
        for (int d4 = 0; d4 < 16; d4++) {
            float4 v;
            v.x = (o[d4*4+0] * a0 + rr[2 + d4*4+0] * a1) * inv;
            v.y = (o[d4*4+1] * a0 + rr[2 + d4*4+1] * a1) * inv;
            v.z = (o[d4*4+2] * a0 + rr[2 + d4*4+2] * a1) * inv;
            v.w = (o[d4*4+3] * a0 + rr[2 + d4*4+3] * a1) * inv;
            ((float4*)og)[d4] = v;
        }
    }
    (void)out_g;
}

// ---------------------------------------------------------------------------
extern "C" void kernel_launch(void* const* d_in, const int* in_sizes, int n_in,
                              void* d_out, int out_size)
{
    const float* hidden = (const float*)d_in[0];
    const float* wqkv   = (const float*)d_in[1];
    const float* wo     = (const float*)d_in[2];
    const int*   pos    = (const int*)d_in[4];
    float*       out    = (float*)d_out;

    float *qkv_ptr, *attn_ptr;
    cudaGetSymbolAddress((void**)&qkv_ptr,  g_qkv);
    cudaGetSymbolAddress((void**)&attn_ptr, g_attn);

    cudaFuncSetAttribute(gemm_mma_tf32, cudaFuncAttributeMaxDynamicSharedMemorySize, GEMM_SMEM);
    cudaFuncSetAttribute(attn_kernel, cudaFuncAttributeMaxDynamicSharedMemorySize, ATTN_SMEM);

    // 1) QKV = hidden @ Wqkv^T    [4096,2304]
    gemm_mma_tf32<<<dim3(QKVD / 128, NTOK / 128), 256, GEMM_SMEM>>>(hidden, wqkv, qkv_ptr,
                                                                    NTOK, QKVD, DD);
    // 2) fused RoPE + sliding-window attention -> g_attn [4096,768]
    attn_kernel<<<dim3(SS / 128, BB * HH), 256, ATTN_SMEM>>>(pos, attn_ptr);
    // 3) out = g_attn @ Wo^T      [4096,768]
    gemm_mma_tf32<<<dim3(DD / 128, NTOK / 128), 256, GEMM_SMEM>>>(attn_ptr, wo, out,
                                                                  NTOK, DD, DD);
}

// round 4
// speedup vs baseline: 2.6440x; 1.2932x over previous
#include <cuda_runtime.h>
#include <math.h>
#include <stdint.h>

// Problem constants
#define BB   2
#define SS   2048
#define DD   768
#define HH   12
#define HDIM 64
#define QKVD 2304           // 3*D per token
#define NTOK (BB*SS)        // 4096

// Scratch (allocation-free rule: __device__ globals)
__device__ float g_qkv[(size_t)NTOK * QKVD];   // [4096, 2304]
__device__ float g_attn[(size_t)NTOK * DD];    // [4096, 768]

__device__ __forceinline__ float to_tf32(float x) {
    uint32_t u;
    asm("cvt.rna.tf32.f32 %0, %1;" : "=r"(u) : "f"(x));
    return __uint_as_float(u);
}

__device__ __forceinline__ void mma_tf32(float c[4], const uint32_t a[4], const uint32_t b[2]) {
    asm volatile(
        "mma.sync.aligned.m16n8k8.row.col.f32.tf32.tf32.f32 "
        "{%0,%1,%2,%3}, {%4,%5,%6,%7}, {%8,%9}, {%0,%1,%2,%3};"
        : "+f"(c[0]), "+f"(c[1]), "+f"(c[2]), "+f"(c[3])
        : "r"(a[0]), "r"(a[1]), "r"(a[2]), "r"(a[3]), "r"(b[0]), "r"(b[1]));
}

// ---------------------------------------------------------------------------
// tf32 mma.sync GEMM NT: C[M,N] = A[M,K] * B[N,K]^T  (unchanged from round 3)
// ---------------------------------------------------------------------------
#define ASUB 132
#define BSUB 68
#define AOFF 0
#define BOFF (32 * ASUB)
#define BUFF (32 * ASUB + 64 * BSUB)
#define GEMM_SMEM (2 * BUFF * 4)

__global__ __launch_bounds__(256, 1) void gemm_mma_tf32(const float* __restrict__ A,
                                                        const float* __restrict__ B,
                                                        float* __restrict__ C,
                                                        int M, int N, int K)
{
    extern __shared__ float smf[];
    const int tid    = threadIdx.x;
    const int wid    = tid >> 5;
    const int lane   = tid & 31;
    const int bm     = blockIdx.y * 128;
    const int bn     = blockIdx.x * 128;
    const int warp_m = wid >> 2;
    const int warp_n = wid & 3;

    float acc[4][4][4];
#pragma unroll
    for (int a = 0; a < 4; a++)
#pragma unroll
        for (int b = 0; b < 4; b++)
#pragma unroll
            for (int r = 0; r < 4; r++) acc[a][b][r] = 0.f;

    const int r0 = tid >> 3;
    const int c4 = tid & 7;
    const int ki_st = c4 >> 1;
    const int qpar  = c4 & 1;

    int stA[4], stB[4];
    const float* gA[4];
    const float* gB[4];
#pragma unroll
    for (int i = 0; i < 4; i++) {
        const int r  = r0 + 32 * i;
        const int mi = r >> 4, rr = r & 15;
        const int ni = r >> 3, nn = r & 7;
        stA[i] = AOFF + (mi * 4 + ki_st) * ASUB + (rr & 7) * 16 + (rr >> 3) + 2 * qpar;
        stB[i] = BOFF + (ni * 4 + ki_st) * BSUB + nn * 8 + qpar;
        gA[i]  = A + (size_t)(bm + r) * K + c4 * 4;
        gB[i]  = B + (size_t)(bn + r) * K + c4 * 4;
    }

    int afb[4], bfb[4];
#pragma unroll
    for (int a = 0; a < 4; a++)
        afb[a] = AOFF + (warp_m * 4 + a) * 4 * ASUB + lane * 4;
#pragma unroll
    for (int b = 0; b < 4; b++)
        bfb[b] = BOFF + (warp_n * 4 + b) * 4 * BSUB + lane * 2;

    const int nchunks = K >> 5;
    float4 la[4], lb[4];

#pragma unroll
    for (int i = 0; i < 4; i++) {
        la[i] = *(const float4*)gA[i];
        lb[i] = *(const float4*)gB[i];
    }
    {
        float* s = smf;
#pragma unroll
        for (int i = 0; i < 4; i++) {
            s[stA[i] + 0]  = to_tf32(la[i].x);
            s[stA[i] + 4]  = to_tf32(la[i].y);
            s[stA[i] + 8]  = to_tf32(la[i].z);
            s[stA[i] + 12] = to_tf32(la[i].w);
            s[stB[i] + 0]  = to_tf32(lb[i].x);
            s[stB[i] + 2]  = to_tf32(lb[i].y);
            s[stB[i] + 4]  = to_tf32(lb[i].z);
            s[stB[i] + 6]  = to_tf32(lb[i].w);
        }
    }
    __syncthreads();

    for (int c = 0; c < nchunks; c++) {
        if (c + 1 < nchunks) {
            const int off = (c + 1) * 32;
#pragma unroll
            for (int i = 0; i < 4; i++) {
                la[i] = *(const float4*)(gA[i] + off);
                lb[i] = *(const float4*)(gB[i] + off);
            }
        }

        const float* s = smf + (c & 1) * BUFF;
#pragma unroll
        for (int ki = 0; ki < 4; ki++) {
            uint32_t af[4][4], bf[4][2];
#pragma unroll
            for (int a = 0; a < 4; a++) {
                float4 v = *(const float4*)(s + afb[a] + ki * ASUB);
                af[a][0] = __float_as_uint(v.x);
                af[a][1] = __float_as_uint(v.y);
                af[a][2] = __float_as_uint(v.z);
                af[a][3] = __float_as_uint(v.w);
            }
#pragma unroll
            for (int b = 0; b < 4; b++) {
                float2 v = *(const float2*)(s + bfb[b] + ki * BSUB);
                bf[b][0] = __float_as_uint(v.x);
                bf[b][1] = __float_as_uint(v.y);
            }
#pragma unroll
            for (int a = 0; a < 4; a++)
#pragma unroll
                for (int b = 0; b < 4; b++)
                    mma_tf32(acc[a][b], af[a], bf[b]);
        }

        if (c + 1 < nchunks) {
            float* d = smf + ((c + 1) & 1) * BUFF;
#pragma unroll
            for (int i = 0; i < 4; i++) {
                d[stA[i] + 0]  = to_tf32(la[i].x);
                d[stA[i] + 4]  = to_tf32(la[i].y);
                d[stA[i] + 8]  = to_tf32(la[i].z);
                d[stA[i] + 12] = to_tf32(la[i].w);
                d[stB[i] + 0]  = to_tf32(lb[i].x);
                d[stB[i] + 2]  = to_tf32(lb[i].y);
                d[stB[i] + 4]  = to_tf32(lb[i].z);
                d[stB[i] + 6]  = to_tf32(lb[i].w);
            }
            __syncthreads();
        }
    }

    const int g = lane >> 2, t = lane & 3;
#pragma unroll
    for (int a = 0; a < 4; a++) {
        const int row = bm + warp_m * 64 + a * 16 + g;
#pragma unroll
        for (int b = 0; b < 4; b++) {
            const int col = bn + warp_n * 32 + b * 8 + 2 * t;
            *(float2*)(C + (size_t)row * N + col)       = make_float2(acc[a][b][0], acc[a][b][1]);
            *(float2*)(C + (size_t)(row + 8) * N + col) = make_float2(acc[a][b][2], acc[a][b][3]);
        }
    }
}

// ---------------------------------------------------------------------------
// Fused RoPE + sliding-window attention on mma.sync tf32.
// grid (16, 24), 256 threads. Warp w owns q-rows 16w..16w+15; processes its
// 3 live 64-key chunks with online softmax, P round-trip through smem.
// ---------------------------------------------------------------------------
#define KPITCH 68
#define VPITCH 72
#define QPITCH 68
#define KOFF 0
#define VOFF (256 * KPITCH)               // 17408 floats
#define QOFF (VOFF + 256 * VPITCH)        // 35840 floats
#define ATTN_SMEM ((QOFF + 128 * QPITCH) * 4)   // 178176 bytes

__device__ __forceinline__ void rope4(int i, float pos, float4 x, float4 y,
                                      float4& lo, float4& hi)
{
    const float FCOEF = -0.41524101186091903f;  // -log2(10000)/32
    float f, sn, cs;
    f = pos * exp2f((float)(4 * i + 0) * FCOEF); sincosf(f, &sn, &cs);
    lo.x = x.x * cs - y.x * sn;  hi.x = y.x * cs + x.x * sn;
    f = pos * exp2f((float)(4 * i + 1) * FCOEF); sincosf(f, &sn, &cs);
    lo.y = x.y * cs - y.y * sn;  hi.y = y.y * cs + x.y * sn;
    f = pos * exp2f((float)(4 * i + 2) * FCOEF); sincosf(f, &sn, &cs);
    lo.z = x.z * cs - y.z * sn;  hi.z = y.z * cs + x.z * sn;
    f = pos * exp2f((float)(4 * i + 3) * FCOEF); sincosf(f, &sn, &cs);
    lo.w = x.w * cs - y.w * sn;  hi.w = y.w * cs + x.w * sn;
}

__device__ __forceinline__ float4 tf32_4(float4 v) {
    v.x = to_tf32(v.x); v.y = to_tf32(v.y); v.z = to_tf32(v.z); v.w = to_tf32(v.w);
    return v;
}

__global__ __launch_bounds__(256) void attn_mma(const int* __restrict__ pos_ids)
{
    extern __shared__ float sm[];
    float* Ks = sm + KOFF;
    float* Vs = sm + VOFF;
    float* Qs = sm + QOFF;

    const int tid  = threadIdx.x;
    const int lane = tid & 31;
    const int w    = tid >> 5;
    const int qb   = blockIdx.x;
    const int bh   = blockIdx.y;
    const int b    = bh / HH;
    const int h    = bh % HH;
    const int kstart = qb * 128 - 64;

    // ---- Phase A: stage K (RoPE, tf32), V (tf32), Q (RoPE, scaled, tf32) ----
    {
        const int r  = tid;                // one K/V row per thread
        const int kg = kstart + r;
        float* kd = Ks + r * KPITCH;
        float* vd = Vs + r * VPITCH;
        if (kg >= 0 && kg < SS) {
            const float* kp = g_qkv + ((size_t)(b * SS + kg)) * QKVD + DD + h * HDIM;
            const float* vp = kp + DD;
            float pos = (float)pos_ids[b * SS + kg];
#pragma unroll
            for (int i = 0; i < 8; i++) {
                float4 x = ((const float4*)kp)[i];
                float4 y = ((const float4*)kp)[i + 8];
                float4 lo, hi;
                rope4(i, pos, x, y, lo, hi);
                ((float4*)kd)[i]     = tf32_4(lo);
                ((float4*)kd)[i + 8] = tf32_4(hi);
            }
#pragma unroll
            for (int i = 0; i < 16; i++)
                ((float4*)vd)[i] = tf32_4(((const float4*)vp)[i]);
        } else {
            // V must be zero so p(=0) * V stays 0; K rows are masked post-MMA.
#pragma unroll
            for (int i = 0; i < 16; i++)
                ((float4*)vd)[i] = make_float4(0.f, 0.f, 0.f, 0.f);
        }
        if (tid < 128) {
            const int qg = qb * 128 + tid;
            const float* qp = g_qkv + ((size_t)(b * SS + qg)) * QKVD + h * HDIM;
            float pos = (float)pos_ids[b * SS + qg];
            float* qd = Qs + tid * QPITCH;
            const float QSC = 0.125f * 1.4426950408889634f;  // scale * log2(e)
#pragma unroll
            for (int i = 0; i < 8; i++) {
                float4 x = ((const float4*)qp)[i];
                float4 y = ((const float4*)qp)[i + 8];
                float4 lo, hi;
                rope4(i, pos, x, y, lo, hi);
                lo.x *= QSC; lo.y *= QSC; lo.z *= QSC; lo.w *= QSC;
                hi.x *= QSC; hi.y *= QSC; hi.z *= QSC; hi.w *= QSC;
                ((float4*)qd)[i]     = tf32_4(lo);
                ((float4*)qd)[i + 8] = tf32_4(hi);
            }
        }
    }
    __syncthreads();

    // ---- Q A-fragments into registers (warp reads only its own 16 rows) ----
    const int rl = (w << 4) + (lane >> 2);   // low local row of this lane
    const int cq = lane & 3;
    uint32_t aq[8][4];
#pragma unroll
    for (int s = 0; s < 8; s++) {
        aq[s][0] = __float_as_uint(Qs[rl * QPITCH + cq + 8 * s]);
        aq[s][1] = __float_as_uint(Qs[(rl + 8) * QPITCH + cq + 8 * s]);
        aq[s][2] = __float_as_uint(Qs[rl * QPITCH + cq + 8 * s + 4]);
        aq[s][3] = __float_as_uint(Qs[(rl + 8) * QPITCH + cq + 8 * s + 4]);
    }
    __syncwarp();

    float m0 = -1e4f, m1 = -1e4f, l0 = 0.f, l1 = 0.f;
    float oacc[8][4];
#pragma unroll
    for (int d = 0; d < 8; d++)
#pragma unroll
        for (int r = 0; r < 4; r++) oacc[d][r] = 0.f;

    float* Pw = Qs + (w << 4) * QPITCH;      // per-warp P region (reuses Q rows)
    const int cw = (w >= 4) ? 1 : 0;

    for (int ci = 0; ci < 3; ci++) {
        const int kbase = (cw + ci) * 64;

        // ---- S = Q @ K^T over this 64-key chunk ----
        float sacc[8][4];
#pragma unroll
        for (int j = 0; j < 8; j++)
#pragma unroll
            for (int r = 0; r < 4; r++) sacc[j][r] = 0.f;

        const float* kb[8];
#pragma unroll
        for (int jt = 0; jt < 8; jt++)
            kb[jt] = Ks + (kbase + 8 * jt + (lane >> 2)) * KPITCH + (lane & 3);

#pragma unroll
        for (int s = 0; s < 8; s++) {
#pragma unroll
            for (int jt = 0; jt < 8; jt++) {
                uint32_t bk[2];
                bk[0] = __float_as_uint(kb[jt][8 * s]);
                bk[1] = __float_as_uint(kb[jt][8 * s + 4]);
                mma_tf32(sacc[jt], aq[s], bk);
            }
        }

        // ---- mask + per-row chunk max ----
        float mx0 = -30000.f, mx1 = -30000.f;
#pragma unroll
        for (int jt = 0; jt < 8; jt++) {
            const int k0 = kbase + 8 * jt + 2 * (lane & 3);
            const int k1 = k0 + 1;
            const int kg0 = kstart + k0, kg1 = kstart + k1;
            const bool in0 = (kg0 >= 0) & (kg0 < SS);
            const bool in1 = (kg1 >= 0) & (kg1 < SS);
            const bool v00 = in0 && ((unsigned)(k0 - rl) <= 128u);
            const bool v01 = in1 && ((unsigned)(k1 - rl) <= 128u);
            const bool v10 = in0 && ((unsigned)(k0 - rl - 8) <= 128u);
            const bool v11 = in1 && ((unsigned)(k1 - rl - 8) <= 128u);
            sacc[jt][0] = v00 ? sacc[jt][0] : -30000.f;
            sacc[jt][1] = v01 ? sacc[jt][1] : -30000.f;
            sacc[jt][2] = v10 ? sacc[jt][2] : -30000.f;
            sacc[jt][3] = v11 ? sacc[jt][3] : -30000.f;
            mx0 = fmaxf(mx0, fmaxf(sacc[jt][0], sacc[jt][1]));
            mx1 = fmaxf(mx1, fmaxf(sacc[jt][2], sacc[jt][3]));
        }
        mx0 = fmaxf(mx0, __shfl_xor_sync(0xffffffff, mx0, 1));
        mx0 = fmaxf(mx0, __shfl_xor_sync(0xffffffff, mx0, 2));
        mx1 = fmaxf(mx1, __shfl_xor_sync(0xffffffff, mx1, 1));
        mx1 = fmaxf(mx1, __shfl_xor_sync(0xffffffff, mx1, 2));

        const float m0n = fmaxf(m0, mx0);
        const float m1n = fmaxf(m1, mx1);
        const float a0 = exp2f(m0 - m0n);
        const float a1 = exp2f(m1 - m1n);
        m0 = m0n; m1 = m1n;
        l0 *= a0; l1 *= a1;
#pragma unroll
        for (int d = 0; d < 8; d++) {
            oacc[d][0] *= a0; oacc[d][1] *= a0;
            oacc[d][2] *= a1; oacc[d][3] *= a1;
        }

        // ---- p = exp2(s - m), rna-rounded; store to Pw; row-sums ----
        float rs0 = 0.f, rs1 = 0.f;
        const int prow = (lane >> 2);
#pragma unroll
        for (int jt = 0; jt < 8; jt++) {
            float p00 = to_tf32(exp2f(sacc[jt][0] - m0));
            float p01 = to_tf32(exp2f(sacc[jt][1] - m0));
            float p10 = to_tf32(exp2f(sacc[jt][2] - m1));
            float p11 = to_tf32(exp2f(sacc[jt][3] - m1));
            rs0 += p00 + p01;
            rs1 += p10 + p11;
            const int pc = 8 * jt + 2 * (lane & 3);
            *(float2*)(Pw + prow * QPITCH + pc)       = make_float2(p00, p01);
            *(float2*)(Pw + (prow + 8) * QPITCH + pc) = make_float2(p10, p11);
        }
        rs0 += __shfl_xor_sync(0xffffffff, rs0, 1);
        rs0 += __shfl_xor_sync(0xffffffff, rs0, 2);
        rs1 += __shfl_xor_sync(0xffffffff, rs1, 1);
        rs1 += __shfl_xor_sync(0xffffffff, rs1, 2);
        l0 += rs0; l1 += rs1;
        __syncwarp();

        // ---- O += P @ V ----
#pragma unroll
        for (int s = 0; s < 8; s++) {
            uint32_t pa[4];
            const float* pb = Pw + prow * QPITCH + (lane & 3) + 8 * s;
            pa[0] = __float_as_uint(pb[0]);
            pa[1] = __float_as_uint(pb[8 * QPITCH]);
            pa[2] = __float_as_uint(pb[4]);
            pa[3] = __float_as_uint(pb[8 * QPITCH + 4]);
            const float* vb = Vs + (kbase + 8 * s + (lane & 3)) * VPITCH + (lane >> 2);
#pragma unroll
            for (int dt = 0; dt < 8; dt++) {
                uint32_t bv[2];
                bv[0] = __float_as_uint(vb[8 * dt]);
                bv[1] = __float_as_uint(vb[4 * VPITCH + 8 * dt]);
                mma_tf32(oacc[dt], pa, bv);
            }
        }
        __syncwarp();
    }

    // ---- normalize + write ----
    const float inv0 = 1.f / l0;
    const float inv1 = 1.f / l1;
    const int rg = qb * 128 + rl;
    float* og0 = g_attn + ((size_t)(b * SS + rg)) * DD + h * HDIM;
    float* og1 = og0 + 8 * DD;
#pragma unroll
    for (int dt = 0; dt < 8; dt++) {
        const int col = 8 * dt + 2 * (lane & 3);
        *(float2*)(og0 + col) = make_float2(oacc[dt][0] * inv0, oacc[dt][1] * inv0);
        *(float2*)(og1 + col) = make_float2(oacc[dt][2] * inv1, oacc[dt][3] * inv1);
    }
}

// ---------------------------------------------------------------------------
extern "C" void kernel_launch(void* const* d_in, const int* in_sizes, int n_in,
                              void* d_out, int out_size)
{
    const float* hidden = (const float*)d_in[0];
    const float* wqkv   = (const float*)d_in[1];
    const float* wo     = (const float*)d_in[2];
    const int*   pos    = (const int*)d_in[4];
    float*       out    = (float*)d_out;

    float *qkv_ptr, *attn_ptr;
    cudaGetSymbolAddress((void**)&qkv_ptr,  g_qkv);
    cudaGetSymbolAddress((void**)&attn_ptr, g_attn);

    cudaFuncSetAttribute(gemm_mma_tf32, cudaFuncAttributeMaxDynamicSharedMemorySize, GEMM_SMEM);
    cudaFuncSetAttribute(attn_mma, cudaFuncAttributeMaxDynamicSharedMemorySize, ATTN_SMEM);

    // 1) QKV = hidden @ Wqkv^T    [4096,2304]
    gemm_mma_tf32<<<dim3(QKVD / 128, NTOK / 128), 256, GEMM_SMEM>>>(hidden, wqkv, qkv_ptr,
                                                                    NTOK, QKVD, DD);
    // 2) fused RoPE + sliding-window attention (tensor cores) -> g_attn
    attn_mma<<<dim3(SS / 128, BB * HH), 256, ATTN_SMEM>>>(pos);
    // 3) out = g_attn @ Wo^T      [4096,768]
    gemm_mma_tf32<<<dim3(DD / 128, NTOK / 128), 256, GEMM_SMEM>>>(attn_ptr, wo, out,
                                                                  NTOK, DD, DD);
}

// round 5
// speedup vs baseline: 2.8598x; 1.0816x over previous
#include <cuda_runtime.h>
#include <math.h>
#include <stdint.h>

// Problem constants
#define BB   2
#define SS   2048
#define DD   768
#define HH   12
#define HDIM 64
#define QKVD 2304           // 3*D per token
#define NTOK (BB*SS)        // 4096

// Scratch (allocation-free rule: __device__ globals)
__device__ float g_qkv[(size_t)NTOK * QKVD];   // [4096, 2304]
__device__ float g_attn[(size_t)NTOK * DD];    // [4096, 768]
__device__ float g_rope[(size_t)NTOK * 64];    // [token][cos32|sin32]

__device__ __forceinline__ float to_tf32(float x) {
    uint32_t u;
    asm("cvt.rna.tf32.f32 %0, %1;" : "=r"(u) : "f"(x));
    return __uint_as_float(u);
}

__device__ __forceinline__ void mma_tf32(float c[4], const uint32_t a[4], const uint32_t b[2]) {
    asm volatile(
        "mma.sync.aligned.m16n8k8.row.col.f32.tf32.tf32.f32 "
        "{%0,%1,%2,%3}, {%4,%5,%6,%7}, {%8,%9}, {%0,%1,%2,%3};"
        : "+f"(c[0]), "+f"(c[1]), "+f"(c[2]), "+f"(c[3])
        : "r"(a[0]), "r"(a[1]), "r"(a[2]), "r"(a[3]), "r"(b[0]), "r"(b[1]));
}

// ---------------------------------------------------------------------------
// RoPE table: g_rope[token*64 + d] = cos(pos*invf[d]), +32 = sin. d = 0..31.
// ---------------------------------------------------------------------------
__global__ void rope_table(const int* __restrict__ pos_ids)
{
    const int idx = blockIdx.x * 256 + threadIdx.x;      // over NTOK*32
    if (idx >= NTOK * 32) return;
    const int bs = idx >> 5;
    const int d  = idx & 31;
    const float FCOEF = -0.41524101186091903f;           // -log2(10000)/32
    const float pos = (float)pos_ids[bs];
    const float f = pos * exp2f((float)d * FCOEF);
    float sn, cs;
    sincosf(f, &sn, &cs);
    g_rope[(size_t)bs * 64 + d]      = cs;
    g_rope[(size_t)bs * 64 + 32 + d] = sn;
}

// ---------------------------------------------------------------------------
// tf32 mma.sync GEMM NT: C[M,N] = A[M,K] * B[N,K]^T
// CTA 256x128x32, 8 warps (4m x 2n), warp tile 64x64. Fragment-ordered smem,
// B n-subtile pairs interleaved for LDS.128 fragment loads.
// ---------------------------------------------------------------------------
#define ASUB 132                    // A subtile stride (floats); data 128
#define BPAD 140                    // B pair-block stride (floats); data 128
#define BOFFS (64 * ASUB)           // 8448 floats
#define BUFN  (BOFFS + 32 * BPAD)   // 12928 floats / buffer
#define GEMM_SMEM (2 * BUFN * 4)    // 103424 bytes

__global__ __launch_bounds__(256, 1) void gemm_mma_tf32(const float* __restrict__ A,
                                                        const float* __restrict__ B,
                                                        float* __restrict__ C,
                                                        int M, int N, int K)
{
    extern __shared__ float smf[];
    const int tid    = threadIdx.x;
    const int wid    = tid >> 5;
    const int lane   = tid & 31;
    const int bm     = blockIdx.y * 256;
    const int bn     = blockIdx.x * 128;
    const int warp_m = wid >> 1;     // 0..3
    const int warp_n = wid & 1;      // 0..1

    float acc[4][8][4];
#pragma unroll
    for (int a = 0; a < 4; a++)
#pragma unroll
        for (int b = 0; b < 8; b++)
#pragma unroll
            for (int r = 0; r < 4; r++) acc[a][b][r] = 0.f;

    // ---- loader geometry ----
    const int c8 = tid & 7;            // float4 index within 32-k chunk
    const int r0 = tid >> 3;           // 0..31
    const int ki_st = c8 >> 1;         // k-subtile 0..3
    const int qpar  = c8 & 1;

    // A: rows r0+32i (i 0..7); B: rows r0+32j (j 0..3)
    const int rrA  = r0 & 15;
    const int miA0 = r0 >> 4;
    const int stA0 = (miA0 * 4 + ki_st) * ASUB + (rrA & 7) * 16 + (rrA >> 3) + 2 * qpar;
    const int nnB  = r0 & 7;
    const int tB0  = r0 >> 4;
    const int pB   = (r0 >> 3) & 1;
    const int stB0 = BOFFS + (tB0 * 4 + ki_st) * BPAD + nnB * 16 + 2 * pB + qpar;

    const float* gA0 = A + (size_t)(bm + r0) * K + c8 * 4;
    const float* gB0 = B + (size_t)(bn + r0) * K + c8 * 4;
    const size_t rstep = (size_t)32 * K;

    // ---- compute-side fragment bases ----
    const int afb0 = (warp_m * 16) * ASUB + lane * 4;              // +528 per a, +132 per ki
    const int bfb0 = BOFFS + (warp_n * 16) * BPAD + lane * 4;      // +560 per t', +140 per ki

    const int nch = K >> 5;
    float4 la[4], lb[4];

    // ---- prologue: chunk 0 -> buffer 0 ----
#pragma unroll
    for (int h = 0; h < 2; h++) {
#pragma unroll
        for (int i = 0; i < 4; i++)
            la[i] = *(const float4*)(gA0 + (size_t)(h * 4 + i) * rstep);
        if (h == 0)
#pragma unroll
            for (int j = 0; j < 4; j++)
                lb[j] = *(const float4*)(gB0 + (size_t)j * rstep);
#pragma unroll
        for (int i = 0; i < 4; i++) {
            float* s = smf + stA0 + (h * 4 + i) * 1056;
            s[0]  = to_tf32(la[i].x);
            s[4]  = to_tf32(la[i].y);
            s[8]  = to_tf32(la[i].z);
            s[12] = to_tf32(la[i].w);
        }
        if (h == 0)
#pragma unroll
            for (int j = 0; j < 4; j++) {
                float* s = smf + stB0 + j * 1120;
                s[0]  = to_tf32(lb[j].x);
                s[4]  = to_tf32(lb[j].y);
                s[8]  = to_tf32(lb[j].z);
                s[12] = to_tf32(lb[j].w);
            }
    }
    __syncthreads();

#define MMA_KI(sbase, ki) do {                                                   \
    uint32_t af[4][4], bf[8][2];                                                 \
    _Pragma("unroll")                                                            \
    for (int a = 0; a < 4; a++) {                                                \
        float4 v = *(const float4*)((sbase) + afb0 + a * 528 + (ki) * 132);      \
        af[a][0] = __float_as_uint(v.x); af[a][1] = __float_as_uint(v.y);        \
        af[a][2] = __float_as_uint(v.z); af[a][3] = __float_as_uint(v.w);        \
    }                                                                            \
    _Pragma("unroll")                                                            \
    for (int t = 0; t < 4; t++) {                                                \
        float4 v = *(const float4*)((sbase) + bfb0 + t * 560 + (ki) * 140);      \
        bf[2*t][0]   = __float_as_uint(v.x); bf[2*t][1]   = __float_as_uint(v.y);\
        bf[2*t+1][0] = __float_as_uint(v.z); bf[2*t+1][1] = __float_as_uint(v.w);\
    }                                                                            \
    _Pragma("unroll")                                                            \
    for (int a = 0; a < 4; a++)                                                  \
        _Pragma("unroll")                                                        \
        for (int b = 0; b < 8; b++)                                              \
            mma_tf32(acc[a][b], af[a], bf[b]);                                   \
} while (0)

    for (int c = 0; c < nch; c++) {
        const float* s = smf + (c & 1) * BUFN;
        float* d = smf + ((c + 1) & 1) * BUFN;
        const bool more = (c + 1 < nch);
        const int koff = (c + 1) * 32;

        if (more) {
#pragma unroll
            for (int i = 0; i < 4; i++)
                la[i] = *(const float4*)(gA0 + koff + (size_t)i * rstep);
#pragma unroll
            for (int j = 0; j < 4; j++)
                lb[j] = *(const float4*)(gB0 + koff + (size_t)j * rstep);
        }

        MMA_KI(s, 0);

        if (more) {
#pragma unroll
            for (int i = 0; i < 4; i++) {
                float* p = d + stA0 + i * 1056;
                p[0]  = to_tf32(la[i].x);
                p[4]  = to_tf32(la[i].y);
                p[8]  = to_tf32(la[i].z);
                p[12] = to_tf32(la[i].w);
            }
#pragma unroll
            for (int j = 0; j < 4; j++) {
                float* p = d + stB0 + j * 1120;
                p[0]  = to_tf32(lb[j].x);
                p[4]  = to_tf32(lb[j].y);
                p[8]  = to_tf32(lb[j].z);
                p[12] = to_tf32(lb[j].w);
            }
#pragma unroll
            for (int i = 0; i < 4; i++)
                la[i] = *(const float4*)(gA0 + koff + (size_t)(4 + i) * rstep);
        }

        MMA_KI(s, 1);
        MMA_KI(s, 2);

        if (more) {
#pragma unroll
            for (int i = 0; i < 4; i++) {
                float* p = d + stA0 + (4 + i) * 1056;
                p[0]  = to_tf32(la[i].x);
                p[4]  = to_tf32(la[i].y);
                p[8]  = to_tf32(la[i].z);
                p[12] = to_tf32(la[i].w);
            }
        }

        MMA_KI(s, 3);

        if (more) __syncthreads();
    }

    // ---- epilogue ----
    const int g = lane >> 2, u = lane & 3;
#pragma unroll
    for (int a = 0; a < 4; a++) {
        const int row = bm + warp_m * 64 + a * 16 + g;
#pragma unroll
        for (int b = 0; b < 8; b++) {
            const int col = bn + warp_n * 64 + b * 8 + 2 * u;
            *(float2*)(C + (size_t)row * N + col)       = make_float2(acc[a][b][0], acc[a][b][1]);
            *(float2*)(C + (size_t)(row + 8) * N + col) = make_float2(acc[a][b][2], acc[a][b][3]);
        }
    }
}

// ---------------------------------------------------------------------------
// Fused RoPE (table) + sliding-window attention on mma.sync tf32.
// ---------------------------------------------------------------------------
#define KPITCH 68
#define VPITCH 72
#define QPITCH 68
#define KOFF 0
#define VOFF (256 * KPITCH)
#define QOFF (VOFF + 256 * VPITCH)
#define ATTN_SMEM ((QOFF + 128 * QPITCH) * 4)

__device__ __forceinline__ float4 tf32_4(float4 v) {
    v.x = to_tf32(v.x); v.y = to_tf32(v.y); v.z = to_tf32(v.z); v.w = to_tf32(v.w);
    return v;
}

__device__ __forceinline__ void rope4t(float4 cs, float4 sn, float4 x, float4 y,
                                       float4& lo, float4& hi)
{
    lo.x = x.x * cs.x - y.x * sn.x;  hi.x = y.x * cs.x + x.x * sn.x;
    lo.y = x.y * cs.y - y.y * sn.y;  hi.y = y.y * cs.y + x.y * sn.y;
    lo.z = x.z * cs.z - y.z * sn.z;  hi.z = y.z * cs.z + x.z * sn.z;
    lo.w = x.w * cs.w - y.w * sn.w;  hi.w = y.w * cs.w + x.w * sn.w;
}

__global__ __launch_bounds__(256) void attn_mma()
{
    extern __shared__ float sm[];
    float* Ks = sm + KOFF;
    float* Vs = sm + VOFF;
    float* Qs = sm + QOFF;

    const int tid  = threadIdx.x;
    const int lane = tid & 31;
    const int w    = tid >> 5;
    const int qb   = blockIdx.x;
    const int bh   = blockIdx.y;
    const int b    = bh / HH;
    const int h    = bh % HH;
    const int kstart = qb * 128 - 64;

    // ---- Phase A: stage K (RoPE, tf32), V (tf32), Q (RoPE, scaled, tf32) ----
    {
        const int r  = tid;
        const int kg = kstart + r;
        float* kd = Ks + r * KPITCH;
        float* vd = Vs + r * VPITCH;
        if (kg >= 0 && kg < SS) {
            const float* kp = g_qkv + ((size_t)(b * SS + kg)) * QKVD + DD + h * HDIM;
            const float* vp = kp + DD;
            const float* rp = g_rope + ((size_t)(b * SS + kg)) * 64;
#pragma unroll
            for (int i = 0; i < 8; i++) {
                float4 x  = ((const float4*)kp)[i];
                float4 y  = ((const float4*)kp)[i + 8];
                float4 cs = ((const float4*)rp)[i];
                float4 sn = ((const float4*)rp)[i + 8];
                float4 lo, hi;
                rope4t(cs, sn, x, y, lo, hi);
                ((float4*)kd)[i]     = tf32_4(lo);
                ((float4*)kd)[i + 8] = tf32_4(hi);
            }
#pragma unroll
            for (int i = 0; i < 16; i++)
                ((float4*)vd)[i] = tf32_4(((const float4*)vp)[i]);
        } else {
#pragma unroll
            for (int i = 0; i < 16; i++)
                ((float4*)vd)[i] = make_float4(0.f, 0.f, 0.f, 0.f);
        }
        if (tid < 128) {
            const int qg = qb * 128 + tid;
            const float* qp = g_qkv + ((size_t)(b * SS + qg)) * QKVD + h * HDIM;
            const float* rp = g_rope + ((size_t)(b * SS + qg)) * 64;
            float* qd = Qs + tid * QPITCH;
            const float QSC = 0.125f * 1.4426950408889634f;
#pragma unroll
            for (int i = 0; i < 8; i++) {
                float4 x  = ((const float4*)qp)[i];
                float4 y  = ((const float4*)qp)[i + 8];
                float4 cs = ((const float4*)rp)[i];
                float4 sn = ((const float4*)rp)[i + 8];
                float4 lo, hi;
                rope4t(cs, sn, x, y, lo, hi);
                lo.x *= QSC; lo.y *= QSC; lo.z *= QSC; lo.w *= QSC;
                hi.x *= QSC; hi.y *= QSC; hi.z *= QSC; hi.w *= QSC;
                ((float4*)qd)[i]     = tf32_4(lo);
                ((float4*)qd)[i + 8] = tf32_4(hi);
            }
        }
    }
    __syncthreads();

    const int rl = (w << 4) + (lane >> 2);
    const int cq = lane & 3;
    uint32_t aq[8][4];
#pragma unroll
    for (int s = 0; s < 8; s++) {
        aq[s][0] = __float_as_uint(Qs[rl * QPITCH + cq + 8 * s]);
        aq[s][1] = __float_as_uint(Qs[(rl + 8) * QPITCH + cq + 8 * s]);
        aq[s][2] = __float_as_uint(Qs[rl * QPITCH + cq + 8 * s + 4]);
        aq[s][3] = __float_as_uint(Qs[(rl + 8) * QPITCH + cq + 8 * s + 4]);
    }
    __syncwarp();

    float m0 = -1e4f, m1 = -1e4f, l0 = 0.f, l1 = 0.f;
    float oacc[8][4];
#pragma unroll
    for (int d = 0; d < 8; d++)
#pragma unroll
        for (int r = 0; r < 4; r++) oacc[d][r] = 0.f;

    float* Pw = Qs + (w << 4) * QPITCH;
    const int cw = (w >= 4) ? 1 : 0;

    for (int ci = 0; ci < 3; ci++) {
        const int kbase = (cw + ci) * 64;

        float sacc[8][4];
#pragma unroll
        for (int j = 0; j < 8; j++)
#pragma unroll
            for (int r = 0; r < 4; r++) sacc[j][r] = 0.f;

        const float* kb[8];
#pragma unroll
        for (int jt = 0; jt < 8; jt++)
            kb[jt] = Ks + (kbase + 8 * jt + (lane >> 2)) * KPITCH + (lane & 3);

#pragma unroll
        for (int s = 0; s < 8; s++) {
#pragma unroll
            for (int jt = 0; jt < 8; jt++) {
                uint32_t bk[2];
                bk[0] = __float_as_uint(kb[jt][8 * s]);
                bk[1] = __float_as_uint(kb[jt][8 * s + 4]);
                mma_tf32(sacc[jt], aq[s], bk);
            }
        }

        float mx0 = -30000.f, mx1 = -30000.f;
#pragma unroll
        for (int jt = 0; jt < 8; jt++) {
            const int k0 = kbase + 8 * jt + 2 * (lane & 3);
            const int k1 = k0 + 1;
            const int kg0 = kstart + k0, kg1 = kstart + k1;
            const bool in0 = (kg0 >= 0) & (kg0 < SS);
            const bool in1 = (kg1 >= 0) & (kg1 < SS);
            const bool v00 = in0 && ((unsigned)(k0 - rl) <= 128u);
            const bool v01 = in1 && ((unsigned)(k1 - rl) <= 128u);
            const bool v10 = in0 && ((unsigned)(k0 - rl - 8) <= 128u);
            const bool v11 = in1 && ((unsigned)(k1 - rl - 8) <= 128u);
            sacc[jt][0] = v00 ? sacc[jt][0] : -30000.f;
            sacc[jt][1] = v01 ? sacc[jt][1] : -30000.f;
            sacc[jt][2] = v10 ? sacc[jt][2] : -30000.f;
            sacc[jt][3] = v11 ? sacc[jt][3] : -30000.f;
            mx0 = fmaxf(mx0, fmaxf(sacc[jt][0], sacc[jt][1]));
            mx1 = fmaxf(mx1, fmaxf(sacc[jt][2], sacc[jt][3]));
        }
        mx0 = fmaxf(mx0, __shfl_xor_sync(0xffffffff, mx0, 1));
        mx0 = fmaxf(mx0, __shfl_xor_sync(0xffffffff, mx0, 2));
        mx1 = fmaxf(mx1, __shfl_xor_sync(0xffffffff, mx1, 1));
        mx1 = fmaxf(mx1, __shfl_xor_sync(0xffffffff, mx1, 2));

        const float m0n = fmaxf(m0, mx0);
        const float m1n = fmaxf(m1, mx1);
        const float a0 = exp2f(m0 - m0n);
        const float a1 = exp2f(m1 - m1n);
        m0 = m0n; m1 = m1n;
        l0 *= a0; l1 *= a1;
#pragma unroll
        for (int d = 0; d < 8; d++) {
            oacc[d][0] *= a0; oacc[d][1] *= a0;
            oacc[d][2] *= a1; oacc[d][3] *= a1;
        }

        float rs0 = 0.f, rs1 = 0.f;
        const int prow = (lane >> 2);
#pragma unroll
        for (int jt = 0; jt < 8; jt++) {
            float p00 = to_tf32(exp2f(sacc[jt][0] - m0));
            float p01 = to_tf32(exp2f(sacc[jt][1] - m0));
            float p10 = to_tf32(exp2f(sacc[jt][2] - m1));
            float p11 = to_tf32(exp2f(sacc[jt][3] - m1));
            rs0 += p00 + p01;
            rs1 += p10 + p11;
            const int pc = 8 * jt + 2 * (lane & 3);
            *(float2*)(Pw + prow * QPITCH + pc)       = make_float2(p00, p01);
            *(float2*)(Pw + (prow + 8) * QPITCH + pc) = make_float2(p10, p11);
        }
        rs0 += __shfl_xor_sync(0xffffffff, rs0, 1);
        rs0 += __shfl_xor_sync(0xffffffff, rs0, 2);
        rs1 += __shfl_xor_sync(0xffffffff, rs1, 1);
        rs1 += __shfl_xor_sync(0xffffffff, rs1, 2);
        l0 += rs0; l1 += rs1;
        __syncwarp();

#pragma unroll
        for (int s = 0; s < 8; s++) {
            uint32_t pa[4];
            const float* pb = Pw + prow * QPITCH + (lane & 3) + 8 * s;
            pa[0] = __float_as_uint(pb[0]);
            pa[1] = __float_as_uint(pb[8 * QPITCH]);
            pa[2] = __float_as_uint(pb[4]);
            pa[3] = __float_as_uint(pb[8 * QPITCH + 4]);
            const float* vb = Vs + (kbase + 8 * s + (lane & 3)) * VPITCH + (lane >> 2);
#pragma unroll
            for (int dt = 0; dt < 8; dt++) {
                uint32_t bv[2];
                bv[0] = __float_as_uint(vb[8 * dt]);
                bv[1] = __float_as_uint(vb[4 * VPITCH + 8 * dt]);
                mma_tf32(oacc[dt], pa, bv);
            }
        }
        __syncwarp();
    }

    const float inv0 = 1.f / l0;
    const float inv1 = 1.f / l1;
    const int rg = qb * 128 + rl;
    float* og0 = g_attn + ((size_t)(b * SS + rg)) * DD + h * HDIM;
    float* og1 = og0 + 8 * DD;
#pragma unroll
    for (int dt = 0; dt < 8; dt++) {
        const int col = 8 * dt + 2 * (lane & 3);
        *(float2*)(og0 + col) = make_float2(oacc[dt][0] * inv0, oacc[dt][1] * inv0);
        *(float2*)(og1 + col) = make_float2(oacc[dt][2] * inv1, oacc[dt][3] * inv1);
    }
}

// ---------------------------------------------------------------------------
extern "C" void kernel_launch(void* const* d_in, const int* in_sizes, int n_in,
                              void* d_out, int out_size)
{
    const float* hidden = (const float*)d_in[0];
    const float* wqkv   = (const float*)d_in[1];
    const float* wo     = (const float*)d_in[2];
    const int*   pos    = (const int*)d_in[4];
    float*       out    = (float*)d_out;

    float *qkv_ptr, *attn_ptr;
    cudaGetSymbolAddress((void**)&qkv_ptr,  g_qkv);
    cudaGetSymbolAddress((void**)&attn_ptr, g_attn);

    cudaFuncSetAttribute(gemm_mma_tf32, cudaFuncAttributeMaxDynamicSharedMemorySize, GEMM_SMEM);
    cudaFuncSetAttribute(attn_mma, cudaFuncAttributeMaxDynamicSharedMemorySize, ATTN_SMEM);

    // 0) RoPE cos/sin table
    rope_table<<<(NTOK * 32 + 255) / 256, 256>>>(pos);
    // 1) QKV = hidden @ Wqkv^T    [4096,2304]
    gemm_mma_tf32<<<dim3(QKVD / 128, NTOK / 256), 256, GEMM_SMEM>>>(hidden, wqkv, qkv_ptr,
                                                                    NTOK, QKVD, DD);
    // 2) fused RoPE + sliding-window attention (tensor cores) -> g_attn
    attn_mma<<<dim3(SS / 128, BB * HH), 256, ATTN_SMEM>>>();
    // 3) out = g_attn @ Wo^T      [4096,768]
    gemm_mma_tf32<<<dim3(DD / 128, NTOK / 256), 256, GEMM_SMEM>>>(attn_ptr, wo, out,
                                                                  NTOK, DD, DD);
}

// round 6
// speedup vs baseline: 3.3003x; 1.1540x over previous
#include <cuda_runtime.h>
#include <math.h>
#include <stdint.h>

// Problem constants
#define BB   2
#define SS   2048
#define DD   768
#define HH   12
#define HDIM 64
#define QKVD 2304           // 3*D per token
#define NTOK (BB*SS)        // 4096

// Scratch (allocation-free rule: __device__ globals)
__device__ float g_qkv[(size_t)NTOK * QKVD];   // [4096, 2304] row-major fp32
__device__ float g_attn[(size_t)NTOK * DD];    // A-image (tf32) for Wo GEMM
__device__ float g_rope[(size_t)NTOK * 64];    // [token][cos32|sin32]
__device__ float g_hidA[(size_t)NTOK * DD];    // hidden as A-image (tf32)
__device__ float g_wqB[(size_t)QKVD * DD];     // Wqkv as B-image (tf32)
__device__ float g_woB[(size_t)DD * DD];       // Wo as B-image (tf32)

__device__ __forceinline__ float to_tf32(float x) {
    uint32_t u;
    asm("cvt.rna.tf32.f32 %0, %1;" : "=r"(u) : "f"(x));
    return __uint_as_float(u);
}

__device__ __forceinline__ uint32_t smem_u32(const void* p) {
    uint32_t a;
    asm("{ .reg .u64 t; cvta.to.shared.u64 t, %1; cvt.u32.u64 %0, t; }"
        : "=r"(a) : "l"(p));
    return a;
}

__device__ __forceinline__ void mma_tf32(float c[4], const uint32_t a[4], const uint32_t b[2]) {
    asm volatile(
        "mma.sync.aligned.m16n8k8.row.col.f32.tf32.tf32.f32 "
        "{%0,%1,%2,%3}, {%4,%5,%6,%7}, {%8,%9}, {%0,%1,%2,%3};"
        : "+f"(c[0]), "+f"(c[1]), "+f"(c[2]), "+f"(c[3])
        : "r"(a[0]), "r"(a[1]), "r"(a[2]), "r"(a[3]), "r"(b[0]), "r"(b[1]));
}

#define CP_ASYNC16(dst, src) \
    asm volatile("cp.async.cg.shared.global [%0], [%1], 16;" :: "r"(dst), "l"(src))
#define CP_COMMIT() asm volatile("cp.async.commit_group;" ::: "memory")
#define CP_WAIT2()  asm volatile("cp.async.wait_group 2;"  ::: "memory")

// ---------------------------------------------------------------------------
// Tile-image layouts (tf32). Tiles: 128 rows x 32 k-cols = 4096 floats.
// A-image (m16k8 A fragments, per-lane 16B-contiguous):
//   off = tile*4096 + ((mi*4+ki)*32 + lane)*4 + e
//   lane = (rr&7)*4 + (c&3);  e = (rr>>3) + 2*(c>>2)   [rr=r&15, c=k&7]
// B-image (n8k8 B fragments, n-subtile pairs interleaved):
//   off = tile*4096 + ((pr*4+ki)*32 + lane)*4 + e
//   lane = (n&7)*4 + (k&3);   e = 2*((n>>3)&1) + ((k&7)>>2)
// ---------------------------------------------------------------------------
__device__ __forceinline__ size_t aimg_off(int r, int k, int ntileK) {
    const int mt = r >> 7, kc = k >> 5;
    const int mi = (r >> 4) & 7, rr = r & 15;
    const int ki = (k >> 3) & 3, c = k & 7;
    const int lane = ((rr & 7) << 2) + (c & 3);
    const int e = (rr >> 3) + ((c >> 2) << 1);
    return ((size_t)(mt * ntileK + kc) << 12) + (((mi << 2) + ki) << 7) + (lane << 2) + e;
}
__device__ __forceinline__ size_t bimg_off(int n, int k, int ntileK) {
    const int nt = n >> 7, kc = k >> 5;
    const int pr = (n >> 4) & 7, p = (n >> 3) & 1, nn = n & 7;
    const int ki = (k >> 3) & 3;
    const int lane = (nn << 2) + (k & 3);
    const int e = (p << 1) + ((k & 7) >> 2);
    return ((size_t)(nt * ntileK + kc) << 12) + (((pr << 2) + ki) << 7) + (lane << 2) + e;
}

__global__ void xform_a(const float* __restrict__ X, float* __restrict__ img, int R, int K)
{
    const int idx = blockIdx.x * 256 + threadIdx.x;
    const int kq = K >> 2;
    if (idx >= R * kq) return;
    const int r = idx / kq, k = (idx - r * kq) << 2;
    const float4 v = *(const float4*)(X + (size_t)r * K + k);
    const int ntileK = K >> 5;
    img[aimg_off(r, k + 0, ntileK)] = to_tf32(v.x);
    img[aimg_off(r, k + 1, ntileK)] = to_tf32(v.y);
    img[aimg_off(r, k + 2, ntileK)] = to_tf32(v.z);
    img[aimg_off(r, k + 3, ntileK)] = to_tf32(v.w);
}

__global__ void xform_b(const float* __restrict__ X, float* __restrict__ img, int R, int K)
{
    const int idx = blockIdx.x * 256 + threadIdx.x;
    const int kq = K >> 2;
    if (idx >= R * kq) return;
    const int n = idx / kq, k = (idx - n * kq) << 2;
    const float4 v = *(const float4*)(X + (size_t)n * K + k);
    const int ntileK = K >> 5;
    img[bimg_off(n, k + 0, ntileK)] = to_tf32(v.x);
    img[bimg_off(n, k + 1, ntileK)] = to_tf32(v.y);
    img[bimg_off(n, k + 2, ntileK)] = to_tf32(v.z);
    img[bimg_off(n, k + 3, ntileK)] = to_tf32(v.w);
}

// ---------------------------------------------------------------------------
// RoPE table: g_rope[token*64 + d] = cos(pos*invf[d]), +32 = sin. d = 0..31.
// ---------------------------------------------------------------------------
__global__ void rope_table(const int* __restrict__ pos_ids)
{
    const int idx = blockIdx.x * 256 + threadIdx.x;
    if (idx >= NTOK * 32) return;
    const int bs = idx >> 5;
    const int d  = idx & 31;
    const float FCOEF = -0.41524101186091903f;
    const float pos = (float)pos_ids[bs];
    const float f = pos * exp2f((float)d * FCOEF);
    float sn, cs;
    sincosf(f, &sn, &cs);
    g_rope[(size_t)bs * 64 + d]      = cs;
    g_rope[(size_t)bs * 64 + 32 + d] = sn;
}

// ---------------------------------------------------------------------------
// GEMM on tile images: C[M,N] = A * B^T, CTA 128x128x32, cp.async 3-stage.
// 8 warps (2m x 4n), warp tile 64x32. grid = (N/128, M/128).
// ---------------------------------------------------------------------------
#define GEMM_SMEM 98304   // 3 stages x (16KB A + 16KB B)

__global__ __launch_bounds__(256, 2) void gemm_img(const float* __restrict__ Aimg,
                                                   const float* __restrict__ Bimg,
                                                   float* __restrict__ C,
                                                   int N, int ntileK)
{
    extern __shared__ float smf[];
    const uint32_t sbase = smem_u32(smf);
    const int tid    = threadIdx.x;
    const int wid    = tid >> 5;
    const int lane   = tid & 31;
    const int mt     = blockIdx.y;
    const int nt     = blockIdx.x;
    const int warp_m = wid >> 2;   // 0..1
    const int warp_n = wid & 3;    // 0..3

    float acc[4][4][4];
#pragma unroll
    for (int a = 0; a < 4; a++)
#pragma unroll
        for (int b = 0; b < 4; b++)
#pragma unroll
            for (int r = 0; r < 4; r++) acc[a][b][r] = 0.f;

    const int nch = ntileK;

    // --- async copy of one k-chunk into stage (c % 3) ---
    const float* Atile0 = Aimg + ((size_t)(mt * ntileK) << 12) + (tid << 2);
    const float* Btile0 = Bimg + ((size_t)(nt * ntileK) << 12) + (tid << 2);

#define ISSUE(c) do {                                                     \
    if ((c) < nch) {                                                      \
        const float* As_ = Atile0 + ((size_t)(c) << 12);                  \
        const float* Bs_ = Btile0 + ((size_t)(c) << 12);                  \
        uint32_t sa_ = sbase + ((c) % 3) * 32768u + (tid << 4);           \
        uint32_t sb_ = sa_ + 16384u;                                      \
        _Pragma("unroll")                                                 \
        for (int i_ = 0; i_ < 4; i_++) {                                  \
            CP_ASYNC16(sa_ + i_ * 4096u, As_ + i_ * 1024);                \
            CP_ASYNC16(sb_ + i_ * 4096u, Bs_ + i_ * 1024);                \
        }                                                                 \
    }                                                                     \
    CP_COMMIT();                                                          \
} while (0)

    ISSUE(0); ISSUE(1); ISSUE(2);

    const int afo = (warp_m * 16) * 128 + lane * 4;          // +512 per a, +128 per ki
    const int bfo = 4096 + (warp_n * 8) * 128 + lane * 4;    // +512 per pair, +128 per ki

    for (int c = 0; c < nch; c++) {
        CP_WAIT2();
        __syncthreads();

        const float* s = smf + (c % 3) * 8192;
#pragma unroll
        for (int ki = 0; ki < 4; ki++) {
            uint32_t af[4][4], bf[4][2];
#pragma unroll
            for (int a = 0; a < 4; a++) {
                float4 v = *(const float4*)(s + afo + a * 512 + ki * 128);
                af[a][0] = __float_as_uint(v.x); af[a][1] = __float_as_uint(v.y);
                af[a][2] = __float_as_uint(v.z); af[a][3] = __float_as_uint(v.w);
            }
#pragma unroll
            for (int t = 0; t < 2; t++) {
                float4 v = *(const float4*)(s + bfo + t * 512 + ki * 128);
                bf[2*t][0]   = __float_as_uint(v.x); bf[2*t][1]   = __float_as_uint(v.y);
                bf[2*t+1][0] = __float_as_uint(v.z); bf[2*t+1][1] = __float_as_uint(v.w);
            }
#pragma unroll
            for (int a = 0; a < 4; a++)
#pragma unroll
                for (int b = 0; b < 4; b++)
                    mma_tf32(acc[a][b], af[a], bf[b]);
        }
        __syncthreads();
        ISSUE(c + 3);
    }

    // epilogue: row-major fp32 C
    const int g = lane >> 2, u = lane & 3;
#pragma unroll
    for (int a = 0; a < 4; a++) {
        const int row = mt * 128 + warp_m * 64 + a * 16 + g;
#pragma unroll
        for (int b = 0; b < 4; b++) {
            const int col = nt * 128 + warp_n * 32 + b * 8 + 2 * u;
            *(float2*)(C + (size_t)row * N + col)       = make_float2(acc[a][b][0], acc[a][b][1]);
            *(float2*)(C + (size_t)(row + 8) * N + col) = make_float2(acc[a][b][2], acc[a][b][3]);
        }
    }
#undef ISSUE
}

// ---------------------------------------------------------------------------
// Fused RoPE (table) + sliding-window attention on mma.sync tf32.
// Output written directly into A-image layout (tf32) for the Wo GEMM.
// ---------------------------------------------------------------------------
#define KPITCH 68
#define VPITCH 72
#define QPITCH 68
#define KOFF 0
#define VOFF (256 * KPITCH)
#define QOFF (VOFF + 256 * VPITCH)
#define ATTN_SMEM ((QOFF + 128 * QPITCH) * 4)

__device__ __forceinline__ float4 tf32_4(float4 v) {
    v.x = to_tf32(v.x); v.y = to_tf32(v.y); v.z = to_tf32(v.z); v.w = to_tf32(v.w);
    return v;
}

__device__ __forceinline__ void rope4t(float4 cs, float4 sn, float4 x, float4 y,
                                       float4& lo, float4& hi)
{
    lo.x = x.x * cs.x - y.x * sn.x;  hi.x = y.x * cs.x + x.x * sn.x;
    lo.y = x.y * cs.y - y.y * sn.y;  hi.y = y.y * cs.y + x.y * sn.y;
    lo.z = x.z * cs.z - y.z * sn.z;  hi.z = y.z * cs.z + x.z * sn.z;
    lo.w = x.w * cs.w - y.w * sn.w;  hi.w = y.w * cs.w + x.w * sn.w;
}

__global__ __launch_bounds__(256) void attn_mma()
{
    extern __shared__ float sm[];
    float* Ks = sm + KOFF;
    float* Vs = sm + VOFF;
    float* Qs = sm + QOFF;

    const int tid  = threadIdx.x;
    const int lane = tid & 31;
    const int w    = tid >> 5;
    const int qb   = blockIdx.x;
    const int bh   = blockIdx.y;
    const int b    = bh / HH;
    const int h    = bh % HH;
    const int kstart = qb * 128 - 64;

    // ---- Phase A: stage K (RoPE, tf32), V (tf32), Q (RoPE, scaled, tf32) ----
    {
        const int r  = tid;
        const int kg = kstart + r;
        float* kd = Ks + r * KPITCH;
        float* vd = Vs + r * VPITCH;
        if (kg >= 0 && kg < SS) {
            const float* kp = g_qkv + ((size_t)(b * SS + kg)) * QKVD + DD + h * HDIM;
            const float* vp = kp + DD;
            const float* rp = g_rope + ((size_t)(b * SS + kg)) * 64;
#pragma unroll
            for (int i = 0; i < 8; i++) {
                float4 x  = ((const float4*)kp)[i];
                float4 y  = ((const float4*)kp)[i + 8];
                float4 cs = ((const float4*)rp)[i];
                float4 sn = ((const float4*)rp)[i + 8];
                float4 lo, hi;
                rope4t(cs, sn, x, y, lo, hi);
                ((float4*)kd)[i]     = tf32_4(lo);
                ((float4*)kd)[i + 8] = tf32_4(hi);
            }
#pragma unroll
            for (int i = 0; i < 16; i++)
                ((float4*)vd)[i] = tf32_4(((const float4*)vp)[i]);
        } else {
#pragma unroll
            for (int i = 0; i < 16; i++)
                ((float4*)vd)[i] = make_float4(0.f, 0.f, 0.f, 0.f);
        }
        if (tid < 128) {
            const int qg = qb * 128 + tid;
            const float* qp = g_qkv + ((size_t)(b * SS + qg)) * QKVD + h * HDIM;
            const float* rp = g_rope + ((size_t)(b * SS + qg)) * 64;
            float* qd = Qs + tid * QPITCH;
            const float QSC = 0.125f * 1.4426950408889634f;
#pragma unroll
            for (int i = 0; i < 8; i++) {
                float4 x  = ((const float4*)qp)[i];
                float4 y  = ((const float4*)qp)[i + 8];
                float4 cs = ((const float4*)rp)[i];
                float4 sn = ((const float4*)rp)[i + 8];
                float4 lo, hi;
                rope4t(cs, sn, x, y, lo, hi);
                lo.x *= QSC; lo.y *= QSC; lo.z *= QSC; lo.w *= QSC;
                hi.x *= QSC; hi.y *= QSC; hi.z *= QSC; hi.w *= QSC;
                ((float4*)qd)[i]     = tf32_4(lo);
                ((float4*)qd)[i + 8] = tf32_4(hi);
            }
        }
    }
    __syncthreads();

    const int rl = (w << 4) + (lane >> 2);
    const int cq = lane & 3;
    uint32_t aq[8][4];
#pragma unroll
    for (int s = 0; s < 8; s++) {
        aq[s][0] = __float_as_uint(Qs[rl * QPITCH + cq + 8 * s]);
        aq[s][1] = __float_as_uint(Qs[(rl + 8) * QPITCH + cq + 8 * s]);
        aq[s][2] = __float_as_uint(Qs[rl * QPITCH + cq + 8 * s + 4]);
        aq[s][3] = __float_as_uint(Qs[(rl + 8) * QPITCH + cq + 8 * s + 4]);
    }
    __syncwarp();

    float m0 = -1e4f, m1 = -1e4f, l0 = 0.f, l1 = 0.f;
    float oacc[8][4];
#pragma unroll
    for (int d = 0; d < 8; d++)
#pragma unroll
        for (int r = 0; r < 4; r++) oacc[d][r] = 0.f;

    float* Pw = Qs + (w << 4) * QPITCH;
    const int cw = (w >= 4) ? 1 : 0;

    for (int ci = 0; ci < 3; ci++) {
        const int kbase = (cw + ci) * 64;

        float sacc[8][4];
#pragma unroll
        for (int j = 0; j < 8; j++)
#pragma unroll
            for (int r = 0; r < 4; r++) sacc[j][r] = 0.f;

        const float* kb[8];
#pragma unroll
        for (int jt = 0; jt < 8; jt++)
            kb[jt] = Ks + (kbase + 8 * jt + (lane >> 2)) * KPITCH + (lane & 3);

#pragma unroll
        for (int s = 0; s < 8; s++) {
#pragma unroll
            for (int jt = 0; jt < 8; jt++) {
                uint32_t bk[2];
                bk[0] = __float_as_uint(kb[jt][8 * s]);
                bk[1] = __float_as_uint(kb[jt][8 * s + 4]);
                mma_tf32(sacc[jt], aq[s], bk);
            }
        }

        float mx0 = -30000.f, mx1 = -30000.f;
#pragma unroll
        for (int jt = 0; jt < 8; jt++) {
            const int k0 = kbase + 8 * jt + 2 * (lane & 3);
            const int k1 = k0 + 1;
            const int kg0 = kstart + k0, kg1 = kstart + k1;
            const bool in0 = (kg0 >= 0) & (kg0 < SS);
            const bool in1 = (kg1 >= 0) & (kg1 < SS);
            const bool v00 = in0 && ((unsigned)(k0 - rl) <= 128u);
            const bool v01 = in1 && ((unsigned)(k1 - rl) <= 128u);
            const bool v10 = in0 && ((unsigned)(k0 - rl - 8) <= 128u);
            const bool v11 = in1 && ((unsigned)(k1 - rl - 8) <= 128u);
            sacc[jt][0] = v00 ? sacc[jt][0] : -30000.f;
            sacc[jt][1] = v01 ? sacc[jt][1] : -30000.f;
            sacc[jt][2] = v10 ? sacc[jt][2] : -30000.f;
            sacc[jt][3] = v11 ? sacc[jt][3] : -30000.f;
            mx0 = fmaxf(mx0, fmaxf(sacc[jt][0], sacc[jt][1]));
            mx1 = fmaxf(mx1, fmaxf(sacc[jt][2], sacc[jt][3]));
        }
        mx0 = fmaxf(mx0, __shfl_xor_sync(0xffffffff, mx0, 1));
        mx0 = fmaxf(mx0, __shfl_xor_sync(0xffffffff, mx0, 2));
        mx1 = fmaxf(mx1, __shfl_xor_sync(0xffffffff, mx1, 1));
        mx1 = fmaxf(mx1, __shfl_xor_sync(0xffffffff, mx1, 2));

        const float m0n = fmaxf(m0, mx0);
        const float m1n = fmaxf(m1, mx1);
        const float a0 = exp2f(m0 - m0n);
        const float a1 = exp2f(m1 - m1n);
        m0 = m0n; m1 = m1n;
        l0 *= a0; l1 *= a1;
#pragma unroll
        for (int d = 0; d < 8; d++) {
            oacc[d][0] *= a0; oacc[d][1] *= a0;
            oacc[d][2] *= a1; oacc[d][3] *= a1;
        }

        float rs0 = 0.f, rs1 = 0.f;
        const int prow = (lane >> 2);
#pragma unroll
        for (int jt = 0; jt < 8; jt++) {
            float p00 = to_tf32(exp2f(sacc[jt][0] - m0));
            float p01 = to_tf32(exp2f(sacc[jt][1] - m0));
            float p10 = to_tf32(exp2f(sacc[jt][2] - m1));
            float p11 = to_tf32(exp2f(sacc[jt][3] - m1));
            rs0 += p00 + p01;
            rs1 += p10 + p11;
            const int pc = 8 * jt + 2 * (lane & 3);
            *(float2*)(Pw + prow * QPITCH + pc)       = make_float2(p00, p01);
            *(float2*)(Pw + (prow + 8) * QPITCH + pc) = make_float2(p10, p11);
        }
        rs0 += __shfl_xor_sync(0xffffffff, rs0, 1);
        rs0 += __shfl_xor_sync(0xffffffff, rs0, 2);
        rs1 += __shfl_xor_sync(0xffffffff, rs1, 1);
        rs1 += __shfl_xor_sync(0xffffffff, rs1, 2);
        l0 += rs0; l1 += rs1;
        __syncwarp();

#pragma unroll
        for (int s = 0; s < 8; s++) {
            uint32_t pa[4];
            const float* pb = Pw + prow * QPITCH + (lane & 3) + 8 * s;
            pa[0] = __float_as_uint(pb[0]);
            pa[1] = __float_as_uint(pb[8 * QPITCH]);
            pa[2] = __float_as_uint(pb[4]);
            pa[3] = __float_as_uint(pb[8 * QPITCH + 4]);
            const float* vb = Vs + (kbase + 8 * s + (lane & 3)) * VPITCH + (lane >> 2);
#pragma unroll
            for (int dt = 0; dt < 8; dt++) {
                uint32_t bv[2];
                bv[0] = __float_as_uint(vb[8 * dt]);
                bv[1] = __float_as_uint(vb[4 * VPITCH + 8 * dt]);
                mma_tf32(oacc[dt], pa, bv);
            }
        }
        __syncwarp();
    }

    // ---- normalize + write directly into A-image layout (tf32) ----
    const float inv0 = 1.f / l0;
    const float inv1 = 1.f / l1;
    const int rg  = qb * 128 + rl;
    const int r0g = b * SS + rg;
    const int r1g = r0g + 8;
#pragma unroll
    for (int dt = 0; dt < 8; dt++) {
        const int c0 = h * HDIM + 8 * dt + 2 * (lane & 3);
        g_attn[aimg_off(r0g, c0,     24)] = to_tf32(oacc[dt][0] * inv0);
        g_attn[aimg_off(r0g, c0 + 1, 24)] = to_tf32(oacc[dt][1] * inv0);
        g_attn[aimg_off(r1g, c0,     24)] = to_tf32(oacc[dt][2] * inv1);
        g_attn[aimg_off(r1g, c0 + 1, 24)] = to_tf32(oacc[dt][3] * inv1);
    }
}

// ---------------------------------------------------------------------------
extern "C" void kernel_launch(void* const* d_in, const int* in_sizes, int n_in,
                              void* d_out, int out_size)
{
    const float* hidden = (const float*)d_in[0];
    const float* wqkv   = (const float*)d_in[1];
    const float* wo     = (const float*)d_in[2];
    const int*   pos    = (const int*)d_in[4];
    float*       out    = (float*)d_out;

    float *qkv_p, *attn_p, *hidA_p, *wqB_p, *woB_p;
    cudaGetSymbolAddress((void**)&qkv_p,  g_qkv);
    cudaGetSymbolAddress((void**)&attn_p, g_attn);
    cudaGetSymbolAddress((void**)&hidA_p, g_hidA);
    cudaGetSymbolAddress((void**)&wqB_p,  g_wqB);
    cudaGetSymbolAddress((void**)&woB_p,  g_woB);

    cudaFuncSetAttribute(gemm_img, cudaFuncAttributeMaxDynamicSharedMemorySize, GEMM_SMEM);
    cudaFuncSetAttribute(attn_mma, cudaFuncAttributeMaxDynamicSharedMemorySize, ATTN_SMEM);

    // 0) RoPE table + operand transforms (tf32 tile images)
    rope_table<<<(NTOK * 32 + 255) / 256, 256>>>(pos);
    xform_a<<<(NTOK * DD / 4 + 255) / 256, 256>>>(hidden, hidA_p, NTOK, DD);
    xform_b<<<(QKVD * DD / 4 + 255) / 256, 256>>>(wqkv, wqB_p, QKVD, DD);
    xform_b<<<(DD * DD / 4 + 255) / 256, 256>>>(wo, woB_p, DD, DD);

    // 1) QKV = hidden @ Wqkv^T   [4096, 2304] row-major fp32
    gemm_img<<<dim3(QKVD / 128, NTOK / 128), 256, GEMM_SMEM>>>(hidA_p, wqB_p, qkv_p,
                                                               QKVD, DD / 32);
    // 2) fused RoPE + sliding-window attention -> g_attn (A-image, tf32)
    attn_mma<<<dim3(SS / 128, BB * HH), 256, ATTN_SMEM>>>();
    // 3) out = attn @ Wo^T       [4096, 768] row-major fp32
    gemm_img<<<dim3(DD / 128, NTOK / 128), 256, GEMM_SMEM>>>(attn_p, woB_p, out,
                                                             DD, DD / 32);
}